// round 7
// baseline (speedup 1.0000x reference)
#include <cuda_runtime.h>
#include <math.h>

#define T 128
#define THREADS 512
#define PITCH 129   // +1 float pad; scalar LDS only, conflict-free-ish both phases
#define SMEM_BYTES (T * PITCH * 4)   // 66048

// Uncompress packed strict-upper-triangle vector (row-major, j>i) into a full
// symmetric n x n matrix with unit diagonal.
//   idx(i,j) = i*(n-1) - i*(i-1)/2 + (j - i - 1)
//
// Triangular grid: one block per upper-triangle 128x128 tile (bj >= bi).
// T=128 -> every contiguous read/write burst is 512B (vs 256B at T=64):
// fewer HBM R/W turnarounds per byte, fewer concurrent address streams.
// R5 structure kept: LDG -> forward to STG (upper tile) + stash smem,
// then float4-gather transpose -> STG.128 mirror tile.
__global__ void __launch_bounds__(THREADS, 3)
uncompress_sym_kernel(const float* __restrict__ comp,
                      float* __restrict__ out,
                      int n, int nb) {
    extern __shared__ float s[];

    // Linear block id -> (bi, bj) in the upper triangle (row-major, incl diag).
    // start(bi) = bi*(2*nb - bi + 1)/2
    const int t = blockIdx.x;
    const float ff = (float)nb + 0.5f;
    int bi = (int)(ff - sqrtf(fmaxf(ff * ff - 2.0f * (float)t, 0.0f)));
    if (bi > nb - 1) bi = nb - 1;
    if (bi < 0) bi = 0;
    while (bi + 1 <= nb - 1 && ((bi + 1) * (2 * nb - bi)) / 2 <= t) bi++;
    while (bi > 0 && (bi * (2 * nb - bi + 1)) / 2 > t) bi--;
    const int bj = bi + (t - (bi * (2 * nb - bi + 1)) / 2);

    const int i0 = bi * T;
    const int j0 = bj * T;
    const int tid = threadIdx.x;

    if (bi != bj) {
        // Phase 1: coalesced 512B-row loads from comp; forward to upper-tile
        // stores from registers; stash in smem for the transpose.
        #pragma unroll
        for (int it = 0; it < (T * T) / THREADS; it++) {     // 32 iters
            const int idx = it * THREADS + tid;
            const int r = idx >> 7;        // row within tile (0..127)
            const int c = idx & 127;       // col within tile
            const int i = i0 + r;
            const int j = j0 + c;
            const int ci = i * (n - 1) - ((i * (i - 1)) >> 1) + (j - i - 1);
            const float v = comp[ci];                  // coalesced, 512B/row
            s[r * PITCH + c] = v;
            out[(size_t)i * n + j] = v;                // coalesced, 512B/row
        }
        __syncthreads();
        // Phase 2: mirror tile out[j][i] = tile^T, column gather from smem,
        // STG.128 (i0 + c4 is a multiple of 4; 512B contiguous per row).
        #pragma unroll
        for (int it = 0; it < (T * T) / (THREADS * 4); it++) {  // 8 iters
            const int idx = it * THREADS + tid;
            const int r  = idx >> 5;            // row within mirror tile (0..127)
            const int c4 = (idx & 31) << 2;     // starting col (multiple of 4)
            float4 v;
            v.x = s[(c4 + 0) * PITCH + r];
            v.y = s[(c4 + 1) * PITCH + r];
            v.z = s[(c4 + 2) * PITCH + r];
            v.w = s[(c4 + 3) * PITCH + r];
            *(float4*)&out[(size_t)(j0 + r) * n + (i0 + c4)] = v;
        }
    } else {
        // Diagonal tile (64 of 2144 blocks): load strict upper, mirror in smem.
        #pragma unroll
        for (int it = 0; it < (T * T) / THREADS; it++) {
            const int idx = it * THREADS + tid;
            const int r = idx >> 7;
            const int c = idx & 127;
            const int i = i0 + r;
            const int j = j0 + c;
            float v = 0.0f;
            if (j > i) {
                const int ci = i * (n - 1) - ((i * (i - 1)) >> 1) + (j - i - 1);
                v = comp[ci];
            }
            s[r * PITCH + c] = v;
        }
        __syncthreads();
        #pragma unroll
        for (int it = 0; it < (T * T) / THREADS; it++) {
            const int idx = it * THREADS + tid;
            const int r = idx >> 7;
            const int c = idx & 127;
            float v;
            if (c > r)       v = s[r * PITCH + c];
            else if (c == r) v = 1.0f;
            else             v = s[c * PITCH + r];
            out[(size_t)(i0 + r) * n + (j0 + c)] = v;
        }
    }
}

extern "C" void kernel_launch(void* const* d_in, const int* in_sizes, int n_in,
                              void* d_out, int out_size) {
    const float* comp = (const float*)d_in[0];
    float* out = (float*)d_out;

    // n = round(sqrt(2m)) + 1 — MUST be double: sqrt(2*33550336) = 8191.49998,
    // which rounds to exactly 8191.5 in fp32 and would give n=8193 (OOB).
    const long long m = (long long)in_sizes[0];
    const int n = (int)llround(sqrt(2.0 * (double)m)) + 1;  // 8192
    const int nb = n / T;                                   // 64

    // Dynamic smem > 48KB needs the opt-in attribute. Idempotent, cheap,
    // capture-safe (executes immediately, not a graph node).
    cudaFuncSetAttribute(uncompress_sym_kernel,
                         cudaFuncAttributeMaxDynamicSharedMemorySize, SMEM_BYTES);

    const int nblocks = nb * (nb + 1) / 2;                  // 2080
    uncompress_sym_kernel<<<nblocks, THREADS, SMEM_BYTES>>>(comp, out, n, nb);
}

// round 8
// speedup vs baseline: 1.2590x; 1.2590x over previous
#include <cuda_runtime.h>
#include <math.h>

#define T 64
#define THREADS 256
#define PITCH 65   // +1 float pad; mirror-phase LDS is 2-way conflicted (measured-OK)

// Uncompress packed strict-upper-triangle vector (row-major, j>i) into a full
// symmetric n x n matrix with unit diagonal.
//   idx(i,j) = i*(n-1) - i*(i-1)/2 + (j - i - 1)
//
// Triangular grid: one block per upper-triangle 64x64 tile (bj >= bi).
// R5 structure (best known): LDG -> forward to STG.32 upper tile + smem stash,
// then float4 column-gather -> STG.128 mirror tile.
// R8 deltas: minblocks 8 (occ ~90% with the proven LDG path) and evict-first
// (__stcs) output stores — output is write-once, never re-read.
__global__ void __launch_bounds__(THREADS, 8)
uncompress_sym_kernel(const float* __restrict__ comp,
                      float* __restrict__ out,
                      int n, int nb) {
    __shared__ float s[T * PITCH];

    // Linear block id -> (bi, bj) in the upper triangle (row-major, incl diag).
    // start(bi) = bi*(2*nb - bi + 1)/2
    const int t = blockIdx.x;
    const float ff = (float)nb + 0.5f;
    int bi = (int)(ff - sqrtf(fmaxf(ff * ff - 2.0f * (float)t, 0.0f)));
    if (bi > nb - 1) bi = nb - 1;
    if (bi < 0) bi = 0;
    while (bi + 1 <= nb - 1 && ((bi + 1) * (2 * nb - bi)) / 2 <= t) bi++;
    while (bi > 0 && (bi * (2 * nb - bi + 1)) / 2 > t) bi--;
    const int bj = bi + (t - (bi * (2 * nb - bi + 1)) / 2);

    const int i0 = bi * T;
    const int j0 = bj * T;
    const int tid = threadIdx.x;

    if (bi != bj) {
        // Phase 1: coalesced load from comp, direct upper-tile store, smem stash.
        #pragma unroll
        for (int it = 0; it < (T * T) / THREADS; it++) {
            const int idx = it * THREADS + tid;
            const int r = idx >> 6;       // row within tile
            const int c = idx & 63;       // col within tile
            const int i = i0 + r;
            const int j = j0 + c;
            const int ci = i * (n - 1) - ((i * (i - 1)) >> 1) + (j - i - 1);
            const float v = comp[ci];                 // coalesced (contig in j)
            s[r * PITCH + c] = v;
            __stcs(&out[(size_t)i * n + j], v);       // coalesced, evict-first
        }
        __syncthreads();
        // Phase 2: mirror tile out[j][i] = tile^T, float4 column gather
        // (2-way LDS conflict with PITCH=65), STG.128 evict-first.
        #pragma unroll
        for (int it = 0; it < (T * T) / (THREADS * 4); it++) {
            const int idx = it * THREADS + tid;
            const int r  = idx >> 4;            // row within mirror tile (0..63)
            const int c4 = (idx & 15) << 2;     // starting col (multiple of 4)
            float4 v;
            v.x = s[(c4 + 0) * PITCH + r];
            v.y = s[(c4 + 1) * PITCH + r];
            v.z = s[(c4 + 2) * PITCH + r];
            v.w = s[(c4 + 3) * PITCH + r];
            __stcs((float4*)&out[(size_t)(j0 + r) * n + (i0 + c4)], v);
        }
    } else {
        // Diagonal tile (128 of 8256 blocks): load strict upper, mirror in smem.
        #pragma unroll
        for (int it = 0; it < (T * T) / THREADS; it++) {
            const int idx = it * THREADS + tid;
            const int r = idx >> 6;
            const int c = idx & 63;
            const int i = i0 + r;
            const int j = j0 + c;
            float v = 0.0f;
            if (j > i) {
                const int ci = i * (n - 1) - ((i * (i - 1)) >> 1) + (j - i - 1);
                v = comp[ci];
            }
            s[r * PITCH + c] = v;
        }
        __syncthreads();
        #pragma unroll
        for (int it = 0; it < (T * T) / THREADS; it++) {
            const int idx = it * THREADS + tid;
            const int r = idx >> 6;
            const int c = idx & 63;
            float v;
            if (c > r)       v = s[r * PITCH + c];
            else if (c == r) v = 1.0f;
            else             v = s[c * PITCH + r];
            __stcs(&out[(size_t)(i0 + r) * n + (j0 + c)], v);
        }
    }
}

extern "C" void kernel_launch(void* const* d_in, const int* in_sizes, int n_in,
                              void* d_out, int out_size) {
    const float* comp = (const float*)d_in[0];
    float* out = (float*)d_out;

    // n = round(sqrt(2m)) + 1 — MUST be double: sqrt(2*33550336) = 8191.49998,
    // which rounds to exactly 8191.5 in fp32 and would give n=8193 (OOB).
    const long long m = (long long)in_sizes[0];
    const int n = (int)llround(sqrt(2.0 * (double)m)) + 1;  // 8192
    const int nb = n / T;                                   // 128

    const int nblocks = nb * (nb + 1) / 2;                  // 8256
    uncompress_sym_kernel<<<nblocks, THREADS>>>(comp, out, n, nb);
}

// round 9
// speedup vs baseline: 1.2879x; 1.0230x over previous
#include <cuda_runtime.h>
#include <math.h>

#define T 64
#define THREADS 256
#define PITCH 65   // +1 float pad; mirror-phase LDS is 2-way conflicted (measured-OK)

// Uncompress packed strict-upper-triangle vector (row-major, j>i) into a full
// symmetric n x n matrix with unit diagonal.
//   idx(i,j) = i*(n-1) - i*(i-1)/2 + (j - i - 1)
//
// Triangular grid: one block per upper-triangle 64x64 tile (bj >= bi).
// R5 config (best known: minblocks 6 -> regs 40 -> deep per-thread LDG batch,
// occ ~70%; R4/R8 sweep shows regs-40 is the MLP x occupancy sweet spot):
//   phase 1: LDG -> forward to STG.32 upper tile + smem stash
//   phase 2: float4 column-gather -> STG.128 mirror tile
// R9 delta vs R5: __stcs (evict-first) output stores only — output is
// write-once/never-reread, so shorten its L2 dirty residency.
__global__ void __launch_bounds__(THREADS, 6)
uncompress_sym_kernel(const float* __restrict__ comp,
                      float* __restrict__ out,
                      int n, int nb) {
    __shared__ float s[T * PITCH];

    // Linear block id -> (bi, bj) in the upper triangle (row-major, incl diag).
    // start(bi) = bi*(2*nb - bi + 1)/2
    const int t = blockIdx.x;
    const float ff = (float)nb + 0.5f;
    int bi = (int)(ff - sqrtf(fmaxf(ff * ff - 2.0f * (float)t, 0.0f)));
    if (bi > nb - 1) bi = nb - 1;
    if (bi < 0) bi = 0;
    while (bi + 1 <= nb - 1 && ((bi + 1) * (2 * nb - bi)) / 2 <= t) bi++;
    while (bi > 0 && (bi * (2 * nb - bi + 1)) / 2 > t) bi--;
    const int bj = bi + (t - (bi * (2 * nb - bi + 1)) / 2);

    const int i0 = bi * T;
    const int j0 = bj * T;
    const int tid = threadIdx.x;

    if (bi != bj) {
        // Phase 1: coalesced load from comp, direct upper-tile store, smem stash.
        #pragma unroll
        for (int it = 0; it < (T * T) / THREADS; it++) {
            const int idx = it * THREADS + tid;
            const int r = idx >> 6;       // row within tile
            const int c = idx & 63;       // col within tile
            const int i = i0 + r;
            const int j = j0 + c;
            const int ci = i * (n - 1) - ((i * (i - 1)) >> 1) + (j - i - 1);
            const float v = comp[ci];                 // coalesced (contig in j)
            s[r * PITCH + c] = v;
            __stcs(&out[(size_t)i * n + j], v);       // coalesced, evict-first
        }
        __syncthreads();
        // Phase 2: mirror tile out[j][i] = tile^T, float4 column gather
        // (2-way LDS conflict with PITCH=65), STG.128 evict-first.
        #pragma unroll
        for (int it = 0; it < (T * T) / (THREADS * 4); it++) {
            const int idx = it * THREADS + tid;
            const int r  = idx >> 4;            // row within mirror tile (0..63)
            const int c4 = (idx & 15) << 2;     // starting col (multiple of 4)
            float4 v;
            v.x = s[(c4 + 0) * PITCH + r];
            v.y = s[(c4 + 1) * PITCH + r];
            v.z = s[(c4 + 2) * PITCH + r];
            v.w = s[(c4 + 3) * PITCH + r];
            __stcs((float4*)&out[(size_t)(j0 + r) * n + (i0 + c4)], v);
        }
    } else {
        // Diagonal tile (128 of 8256 blocks): load strict upper, mirror in smem.
        #pragma unroll
        for (int it = 0; it < (T * T) / THREADS; it++) {
            const int idx = it * THREADS + tid;
            const int r = idx >> 6;
            const int c = idx & 63;
            const int i = i0 + r;
            const int j = j0 + c;
            float v = 0.0f;
            if (j > i) {
                const int ci = i * (n - 1) - ((i * (i - 1)) >> 1) + (j - i - 1);
                v = comp[ci];
            }
            s[r * PITCH + c] = v;
        }
        __syncthreads();
        #pragma unroll
        for (int it = 0; it < (T * T) / THREADS; it++) {
            const int idx = it * THREADS + tid;
            const int r = idx >> 6;
            const int c = idx & 63;
            float v;
            if (c > r)       v = s[r * PITCH + c];
            else if (c == r) v = 1.0f;
            else             v = s[c * PITCH + r];
            __stcs(&out[(size_t)(i0 + r) * n + (j0 + c)], v);
        }
    }
}

extern "C" void kernel_launch(void* const* d_in, const int* in_sizes, int n_in,
                              void* d_out, int out_size) {
    const float* comp = (const float*)d_in[0];
    float* out = (float*)d_out;

    // n = round(sqrt(2m)) + 1 — MUST be double: sqrt(2*33550336) = 8191.49998,
    // which rounds to exactly 8191.5 in fp32 and would give n=8193 (OOB).
    const long long m = (long long)in_sizes[0];
    const int n = (int)llround(sqrt(2.0 * (double)m)) + 1;  // 8192
    const int nb = n / T;                                   // 128

    const int nblocks = nb * (nb + 1) / 2;                  // 8256
    uncompress_sym_kernel<<<nblocks, THREADS>>>(comp, out, n, nb);
}